// round 13
// baseline (speedup 1.0000x reference)
#include <cuda_runtime.h>

#define N_NODES 100000
#define HEADS 4
#define HIDDEN 32

// Device-global scratch (no allocation allowed).
// g_acc[h][n] = {Tx, Ty, Tz, S}: heads-major so one edge's 4 reds hit 4
// different L2 slices (per-slice atomic ALU serializes).
__device__ __align__(16) float4 g_acc[HEADS][N_NODES];
__device__ float g_M[HEADS][3][3];       // quadratic form (pre-scaled by 1/sqrt(32))
__device__ float g_L[HEADS][3];          // linear term from biases
__device__ float g_C[HEADS];             // constant term from biases
__device__ float g_A[HEADS][3][HIDDEN];  // Wv_h^T @ Wout_h
__device__ float g_U[HEADS][HIDDEN];     // bv_h @ Wout_h
__device__ int   g_is64;                 // edge_index dtype flag

// ---------------------------------------------------------------------------
// init (single launch):
//   blocks 0..70   : warp-per-output precompute (564 outputs, 32-wide
//                    reductions via shuffle) + 1 detect warp
//   blocks 71..    : zero g_acc, exactly one float4 per thread
// ---------------------------------------------------------------------------
#define PRE_BLOCKS 71
#define NZB ((N_NODES * HEADS + 255) / 256)   // 1563 zero-blocks

__device__ __forceinline__ float warp_sum(float v) {
#pragma unroll
    for (int o = 16; o > 0; o >>= 1) v += __shfl_xor_sync(0xffffffffu, v, o);
    return v;
}

__global__ void init_kernel(const void* __restrict__ ei_raw,
                            const float* __restrict__ Wq, const float* __restrict__ bq,
                            const float* __restrict__ Wk, const float* __restrict__ bk,
                            const float* __restrict__ Wv, const float* __restrict__ bv,
                            const float* __restrict__ Wout, int E) {
    if (blockIdx.x < PRE_BLOCKS) {
        const float scale = rsqrtf((float)HIDDEN);
        int w = (blockIdx.x * blockDim.x + threadIdx.x) >> 5;  // global warp id
        int d = threadIdx.x & 31;                              // lane = reduction index

        if (w < 36) {
            int h = w / 9, i = (w % 9) / 3, j = w % 3;
            float v = Wq[i * 128 + h * 32 + d] * Wk[j * 128 + h * 32 + d];
            v = warp_sum(v);
            if (d == 0) g_M[h][i][j] = v * scale;
        } else if (w < 48) {
            int u = w - 36; int h = u / 3, i = u % 3;
            float v = Wq[i * 128 + h * 32 + d] * bk[h * 32 + d]
                    + Wk[i * 128 + h * 32 + d] * bq[h * 32 + d];
            v = warp_sum(v);
            if (d == 0) g_L[h][i] = v * scale;
        } else if (w < 52) {
            int h = w - 48;
            float v = bq[h * 32 + d] * bk[h * 32 + d];
            v = warp_sum(v);
            if (d == 0) g_C[h] = v * scale;
        } else if (w < 436) {
            int u = w - 52; int h = u / 96; int r = u % 96; int i = r / 32, m = r % 32;
            float v = Wv[i * 128 + h * 32 + d] * Wout[(h * 32 + d) * 32 + m];
            v = warp_sum(v);
            if (d == 0) g_A[h][i][m] = v;
        } else if (w < 564) {
            int u = w - 436; int h = u / 32, m = u % 32;
            float v = bv[h * 32 + d] * Wout[(h * 32 + d) * 32 + m];
            v = warp_sum(v);
            if (d == 0) g_U[h][m] = v;
        } else if (w == 564) {
            // dtype detection: interpret first 128 entries as int64; all being
            // valid node ids identifies a true int64 buffer (for an int32
            // buffer the high words are random indices -> fails w.p. ~1).
            const long long* p = (const long long*)ei_raw;
            int lim = 2 * E < 128 ? 2 * E : 128;
            bool ok = true;
#pragma unroll
            for (int q = 0; q < 4; q++) {
                int idx = d + q * 32;
                if (idx < lim) {
                    long long v = p[idx];
                    if (v < 0 || v >= N_NODES) ok = false;
                }
            }
            unsigned all = __all_sync(0xffffffffu, ok);
            if (d == 0) g_is64 = (int)all;
        }
        return;
    }

    int i = (blockIdx.x - PRE_BLOCKS) * blockDim.x + threadIdx.x;
    if (i < N_NODES * HEADS)
        (&g_acc[0][0])[i] = make_float4(0.f, 0.f, 0.f, 0.f);
}

// ---------------------------------------------------------------------------
// edge kernel: exact R8/R12 body (measured 20.9us). 1 edge/thread, 6 scalar
// gathers (MLP=6), uniform constant LDGs, 4x red.global.add.v4.f32.
// ---------------------------------------------------------------------------
__global__ void edge_kernel(const float* __restrict__ pos,
                            const void* __restrict__ ei_raw, int E) {
    int e = blockIdx.x * blockDim.x + threadIdx.x;
    if (e >= E) return;

    int r, c;
    if (g_is64) {
        const long long* ei = (const long long*)ei_raw;
        r = (int)ei[e];
        c = (int)ei[E + e];
    } else {
        const int* ei = (const int*)ei_raw;
        r = ei[e];
        c = ei[E + e];
    }

    float rx = __ldg(&pos[3 * r + 0]) - __ldg(&pos[3 * c + 0]);
    float ry = __ldg(&pos[3 * r + 1]) - __ldg(&pos[3 * c + 1]);
    float rz = __ldg(&pos[3 * r + 2]) - __ldg(&pos[3 * c + 2]);

    float sc[HEADS];
#pragma unroll
    for (int h = 0; h < HEADS; h++) {
        float qx = rx * g_M[h][0][0] + ry * g_M[h][1][0] + rz * g_M[h][2][0];
        float qy = rx * g_M[h][0][1] + ry * g_M[h][1][1] + rz * g_M[h][2][1];
        float qz = rx * g_M[h][0][2] + ry * g_M[h][1][2] + rz * g_M[h][2][2];
        sc[h] = rx * qx + ry * qy + rz * qz
              + rx * g_L[h][0] + ry * g_L[h][1] + rz * g_L[h][2] + g_C[h];
    }
    float mx = fmaxf(fmaxf(sc[0], sc[1]), fmaxf(sc[2], sc[3]));
    float ex[HEADS];
    float sum = 0.f;
#pragma unroll
    for (int h = 0; h < HEADS; h++) { ex[h] = __expf(sc[h] - mx); sum += ex[h]; }
    float inv = 1.f / sum;

#pragma unroll
    for (int h = 0; h < HEADS; h++) {
        float a = ex[h] * inv;
        float4* p = &g_acc[h][c];
        asm volatile("red.global.add.v4.f32 [%0], {%1, %2, %3, %4};"
                     :: "l"(p), "f"(a * rx), "f"(a * ry), "f"(a * rz), "f"(a)
                     : "memory");
    }
}

// ---------------------------------------------------------------------------
// node kernel: 1 warp/node; 16-float contraction, warp LayerNorm, SiLU.
// ---------------------------------------------------------------------------
__global__ void node_kernel(const float* __restrict__ bout, const float* __restrict__ gamma,
                            const float* __restrict__ beta, float* __restrict__ out) {
    int gtid = blockIdx.x * blockDim.x + threadIdx.x;
    int n = gtid >> 5;
    int lane = gtid & 31;
    if (n >= N_NODES) return;

    float4 t0 = g_acc[0][n];
    float4 t1 = g_acc[1][n];
    float4 t2 = g_acc[2][n];
    float4 t3 = g_acc[3][n];
    // count = sum_h S_h (softmax over heads sums to 1 per edge)
    float cnt = t0.w + t1.w + t2.w + t3.w;
    float invc = 1.f / fmaxf(cnt, 1.f);

    float acc =
          t0.x * g_A[0][0][lane] + t0.y * g_A[0][1][lane] + t0.z * g_A[0][2][lane] + t0.w * g_U[0][lane]
        + t1.x * g_A[1][0][lane] + t1.y * g_A[1][1][lane] + t1.z * g_A[1][2][lane] + t1.w * g_U[1][lane]
        + t2.x * g_A[2][0][lane] + t2.y * g_A[2][1][lane] + t2.z * g_A[2][2][lane] + t2.w * g_U[2][lane]
        + t3.x * g_A[3][0][lane] + t3.y * g_A[3][1][lane] + t3.z * g_A[3][2][lane] + t3.w * g_U[3][lane];

    float val = acc * invc + bout[lane];

    float s = val, ss = val * val;
#pragma unroll
    for (int o = 16; o > 0; o >>= 1) {
        s  += __shfl_xor_sync(0xffffffffu, s, o);
        ss += __shfl_xor_sync(0xffffffffu, ss, o);
    }
    float mu  = s * (1.f / 32.f);
    float var = ss * (1.f / 32.f) - mu * mu;
    float y = (val - mu) * rsqrtf(var + 1e-5f) * gamma[lane] + beta[lane];
    out[n * 32 + lane] = y * (1.f / (1.f + __expf(-y)));
}

extern "C" void kernel_launch(void* const* d_in, const int* in_sizes, int n_in,
                              void* d_out, int out_size) {
    const float* pos   = (const float*)d_in[0];
    const void*  ei    = d_in[1];
    const float* Wq    = (const float*)d_in[2];
    const float* bq    = (const float*)d_in[3];
    const float* Wk    = (const float*)d_in[4];
    const float* bk    = (const float*)d_in[5];
    const float* Wv    = (const float*)d_in[6];
    const float* bv    = (const float*)d_in[7];
    const float* Wout  = (const float*)d_in[8];
    const float* bout  = (const float*)d_in[9];
    const float* gamma = (const float*)d_in[10];
    const float* beta  = (const float*)d_in[11];
    float* out = (float*)d_out;

    int E = in_sizes[1] / 2;

    init_kernel<<<PRE_BLOCKS + NZB, 256>>>(ei, Wq, bq, Wk, bk, Wv, bv, Wout, E);
    edge_kernel<<<(E + 255) / 256, 256>>>(pos, ei, E);
    node_kernel<<<(N_NODES * 32 + 255) / 256, 256>>>(bout, gamma, beta, out);
}